// round 16
// baseline (speedup 1.0000x reference)
#include <cuda_runtime.h>
#include <cuda_fp16.h>
#include <math_constants.h>
#include <mma.h>

using namespace nvcuda;

#define Nn 50000
#define Ee 800000
#define INC 128
#define HEADS 4
#define F1 256
#define OUTC 64
#define NEG 0.2f
#define CAP 96              // bucket capacity per dst (deg ~ Poisson(16))

// gemm1 smem (halfs / floats, padded); C aliases W
#define XLD 136
#define G1LD 136
#define CLD1 132
#define SX_OFF 0            // sX: 64*136*2  = 17408 B
#define SW_OFF 17408        // sW: 128*136*2 = 34816 B ; sC: 64*132*4 = 33792 B
#define SMEM1_BYTES (17408 + 34816)

// gemm2 smem
#define X2LD 264
#define W2LD 72
#define SX2_OFF 0
#define SW2_OFF 33792
#define SMEM2_BYTES (33792 + 36864)

#define FENCINF 0xFFFFFFFFu
#define R8 FENCINF,FENCINF,FENCINF,FENCINF,FENCINF,FENCINF,FENCINF,FENCINF

// ---------------- scratch ----------------
__device__ uint2    g_h1h[Nn * 64];
__device__ uint2    g_x2h[Nn * 64];
__device__ __half   g_h2h[Nn * 64];
__device__ float4   g_ss1[Nn];
__device__ float4   g_sd1[Nn];
__device__ float    g_ss2[Nn];
__device__ float    g_sd2[Nn];
__device__ int      g_cnt[Nn];          // zero-init; re-zeroed by agg2 each call
__device__ int      g_bkt[Nn * CAP];    // src buckets per dst
__device__ unsigned g_minbuf[OUTC] = {R8, R8, R8, R8, R8, R8, R8, R8};
__device__ int      g_done;

__device__ __forceinline__ unsigned fenc(float f) {
    unsigned u = __float_as_uint(f);
    return (u & 0x80000000u) ? ~u : (u | 0x80000000u);
}
__device__ __forceinline__ float fdec(unsigned u) {
    return __uint_as_float((u & 0x80000000u) ? (u & 0x7FFFFFFFu) : ~u);
}
__device__ __forceinline__ float lrelu(float v) { return v > 0.f ? v : NEG * v; }
__device__ __forceinline__ float elu(float v) { return v > 0.f ? v : expm1f(v); }
__device__ __forceinline__ float dot4(float4 a, float4 b) {
    return a.x * b.x + a.y * b.y + a.z * b.z + a.w * b.w;
}
__device__ __forceinline__ uint2 f4_to_h4(float4 v) {
    __half2 a = __floats2half2_rn(v.x, v.y);
    __half2 b = __floats2half2_rn(v.z, v.w);
    uint2 r;
    r.x = *(unsigned*)&a;
    r.y = *(unsigned*)&b;
    return r;
}
__device__ __forceinline__ void acc8(float* acc, float w, uint4 r) {
    float2 f0 = __half22float2(*(__half2*)&r.x);
    float2 f1 = __half22float2(*(__half2*)&r.y);
    float2 f2 = __half22float2(*(__half2*)&r.z);
    float2 f3 = __half22float2(*(__half2*)&r.w);
    acc[0] += w * f0.x; acc[1] += w * f0.y;
    acc[2] += w * f1.x; acc[3] += w * f1.y;
    acc[4] += w * f2.x; acc[5] += w * f2.y;
    acc[6] += w * f3.x; acc[7] += w * f3.y;
}

// ---------------- bucket fill (g_cnt arrives zeroed) ----------------
__global__ void k_fillB(const int4* __restrict__ src4, const int4* __restrict__ dst4) {
    int i = blockIdx.x * blockDim.x + threadIdx.x;
    if (i < Ee / 4) {
        int4 s = src4[i];
        int4 d = dst4[i];
        int p;
        p = atomicAdd(&g_cnt[d.x], 1); if (p < CAP) g_bkt[d.x * CAP + p] = s.x;
        p = atomicAdd(&g_cnt[d.y], 1); if (p < CAP) g_bkt[d.y * CAP + p] = s.y;
        p = atomicAdd(&g_cnt[d.z], 1); if (p < CAP) g_bkt[d.z * CAP + p] = s.z;
        p = atomicAdd(&g_cnt[d.w], 1); if (p < CAP) g_bkt[d.w * CAP + p] = s.w;
    }
}

__global__ void k_nop() {}

// ---------------- layer 1 GEMM: fp16 WMMA, 64 nodes x 128 feats per block ---
__global__ __launch_bounds__(256, 3)
void k_gemm1(const float4* __restrict__ x4, const float4* __restrict__ W14,
             const float4* __restrict__ as4, const float4* __restrict__ ad4) {
    extern __shared__ char smc[];
    __half* sX = (__half*)(smc + SX_OFF);   // [64][136]
    __half* sW = (__half*)(smc + SW_OFF);   // [128][136]
    float*  sC = (float*)(smc + SW_OFF);    // [64][132], aliases sW post-MMA

    int t = threadIdx.x;
    int lane = t & 31;
    int w = t >> 5;
    int n0 = blockIdx.x * 64;
    int fh = blockIdx.y;

#pragma unroll
    for (int i = 0; i < 16; i++) {
        int idx = t + 256 * i;
        int r = idx >> 5, c = idx & 31;
        float4 v = W14[r * 64 + fh * 32 + c];
        *(uint2*)(sW + r * G1LD + c * 4) = f4_to_h4(v);
    }
#pragma unroll
    for (int i = 0; i < 8; i++) {
        int idx = t + 256 * i;
        int n = idx >> 5, c = idx & 31;
        float4 v = (n0 + n < Nn) ? x4[(n0 + n) * 32 + c] : make_float4(0.f, 0.f, 0.f, 0.f);
        *(uint2*)(sX + n * XLD + c * 4) = f4_to_h4(v);
    }
    __syncthreads();

    int wm = w & 1;
    int wn = w >> 1;
    wmma::fragment<wmma::accumulator, 16, 16, 16, float> c[2][2];
#pragma unroll
    for (int i = 0; i < 2; i++)
#pragma unroll
        for (int j = 0; j < 2; j++) wmma::fill_fragment(c[i][j], 0.f);

#pragma unroll
    for (int kk = 0; kk < 8; kk++) {
        wmma::fragment<wmma::matrix_a, 16, 16, 16, __half, wmma::row_major> a[2];
        wmma::fragment<wmma::matrix_b, 16, 16, 16, __half, wmma::row_major> b[2];
#pragma unroll
        for (int i = 0; i < 2; i++)
            wmma::load_matrix_sync(a[i], sX + (wm * 32 + i * 16) * XLD + kk * 16, XLD);
#pragma unroll
        for (int j = 0; j < 2; j++)
            wmma::load_matrix_sync(b[j], sW + (kk * 16) * G1LD + wn * 32 + j * 16, G1LD);
#pragma unroll
        for (int i = 0; i < 2; i++)
#pragma unroll
            for (int j = 0; j < 2; j++)
                wmma::mma_sync(c[i][j], a[i], b[j], c[i][j]);
    }
    __syncthreads();
#pragma unroll
    for (int i = 0; i < 2; i++)
#pragma unroll
        for (int j = 0; j < 2; j++)
            wmma::store_matrix_sync(sC + (wm * 32 + i * 16) * CLD1 + wn * 32 + j * 16,
                                    c[i][j], CLD1, wmma::mem_row_major);
    __syncthreads();

#pragma unroll
    for (int i = 0; i < 8; i++) {
        int idx = t + 256 * i;
        int n = idx >> 5, g = idx & 31;
        if (n0 + n < Nn) {
            float4 v = *(const float4*)(sC + n * CLD1 + g * 4);
            g_h1h[(n0 + n) * 64 + fh * 32 + g] = f4_to_h4(v);
        }
    }

    float* gss = (float*)g_ss1;
    float* gsd = (float*)g_sd1;
#pragma unroll
    for (int i = 0; i < 8; i++) {
        int n = i * 8 + w;
        float4 c4 = *(const float4*)(sC + n * CLD1 + lane * 4);
        float4 a4 = as4[fh * 32 + lane];
        float4 d4 = ad4[fh * 32 + lane];
        float ps = dot4(c4, a4);
        float pd = dot4(c4, d4);
#pragma unroll
        for (int o = 8; o > 0; o >>= 1) {
            ps += __shfl_down_sync(0xFFFFFFFFu, ps, o, 16);
            pd += __shfl_down_sync(0xFFFFFFFFu, pd, o, 16);
        }
        if ((lane & 15) == 0) {
            int head = fh * 2 + (lane >> 4);
            int nn = n0 + n;
            if (nn < Nn) { gss[nn * 4 + head] = ps; gsd[nn * 4 + head] = pd; }
        }
    }
}

// ---------------- layer 1 gather-aggregate: warp/dst, HFMA2 batches ---------
__global__ void k_agg1(const float4* __restrict__ b1_4) {
    int d = (blockIdx.x * blockDim.x + threadIdx.x) >> 5;
    int l = threadIdx.x & 31;
    if (d >= Nn) return;
    int deg = g_cnt[d];
    if (deg > CAP) deg = CAP;
    int h = l >> 3;

    const float* gss = (const float*)g_ss1;
    float sd = ((const float*)g_sd1)[d * 4 + h];
    const uint4* h1r = (const uint4*)g_h1h;
    const int* bkt = g_bkt + d * CAP;

    float wself = __expf(lrelu(gss[d * 4 + h] + sd));
    float acc[8];
    {
        uint4 rs = h1r[d * 32 + l];
#pragma unroll
        for (int i = 0; i < 8; i++) acc[i] = 0.f;
        acc8(acc, wself, rs);
    }
    float den_own = 0.f;
    const __half2 hz = __half2half2(__ushort_as_half(0));

    for (int base = 0; base < deg; base += 32) {
        int sv = (base + l < deg) ? bkt[base + l] : 0;
        int m = deg - base; if (m > 32) m = 32;
        int jj = 0;
        for (; jj + 8 <= m; jj += 8) {
            int s[8];
#pragma unroll
            for (int u = 0; u < 8; u++) s[u] = __shfl_sync(0xFFFFFFFFu, sv, jj + u);
            uint4 r[8];
#pragma unroll
            for (int u = 0; u < 8; u++) r[u] = h1r[s[u] * 32 + l];
            int u0 = l & 7;
            float e = gss[s[u0] * 4 + h];
            float wown = __expf(lrelu(e + sd));
            den_own += wown;
            unsigned wpk;
            { __half2 tt = __half2half2(__float2half_rn(wown)); wpk = *(unsigned*)&tt; }
            __half2 ha0 = hz, ha1 = hz, ha2 = hz, ha3 = hz;
#pragma unroll
            for (int u = 0; u < 8; u++) {
                unsigned wu = __shfl_sync(0xFFFFFFFFu, wpk, (l & 24) | u);
                __half2 w2 = *(__half2*)&wu;
                ha0 = __hfma2(w2, *(__half2*)&r[u].x, ha0);
                ha1 = __hfma2(w2, *(__half2*)&r[u].y, ha1);
                ha2 = __hfma2(w2, *(__half2*)&r[u].z, ha2);
                ha3 = __hfma2(w2, *(__half2*)&r[u].w, ha3);
            }
            float2 f0 = __half22float2(ha0), f1 = __half22float2(ha1);
            float2 f2 = __half22float2(ha2), f3 = __half22float2(ha3);
            acc[0] += f0.x; acc[1] += f0.y; acc[2] += f1.x; acc[3] += f1.y;
            acc[4] += f2.x; acc[5] += f2.y; acc[6] += f3.x; acc[7] += f3.y;
        }
        for (; jj < m; jj++) {
            int s = __shfl_sync(0xFFFFFFFFu, sv, jj);
            float e = gss[s * 4 + h];
            uint4 r = h1r[s * 32 + l];
            float w = __expf(lrelu(e + sd));
            acc8(acc, w, r);
            if ((l & 7) == 0) den_own += w;
        }
    }
    // per-head den: butterfly over the 8-lane head group, then add self
    float den = den_own;
    den += __shfl_xor_sync(0xFFFFFFFFu, den, 1, 8);
    den += __shfl_xor_sync(0xFFFFFFFFu, den, 2, 8);
    den += __shfl_xor_sync(0xFFFFFFFFu, den, 4, 8);
    den += wself;

    float rinv = 1.f / den;
    float4 bA = b1_4[2 * l], bB = b1_4[2 * l + 1];
    float4 oA, oB;
    oA.x = elu(acc[0] * rinv + bA.x); oA.y = elu(acc[1] * rinv + bA.y);
    oA.z = elu(acc[2] * rinv + bA.z); oA.w = elu(acc[3] * rinv + bA.w);
    oB.x = elu(acc[4] * rinv + bB.x); oB.y = elu(acc[5] * rinv + bB.y);
    oB.z = elu(acc[6] * rinv + bB.z); oB.w = elu(acc[7] * rinv + bB.w);
    g_x2h[d * 64 + 2 * l] = f4_to_h4(oA);
    g_x2h[d * 64 + 2 * l + 1] = f4_to_h4(oB);
}

// ---------------- layer 2 GEMM: fp16 WMMA, 64 nodes x 64 feats per block ----
__global__ __launch_bounds__(256, 3)
void k_gemm2(const float4* __restrict__ W24,
             const float* __restrict__ as2, const float* __restrict__ ad2) {
    extern __shared__ char smc[];
    __half* sX2 = (__half*)(smc + SX2_OFF);
    __half* sW2 = (__half*)(smc + SW2_OFF);
    float*  sC2 = (float*)(smc + SW2_OFF);

    int t = threadIdx.x;
    int n0 = blockIdx.x * 64;

#pragma unroll
    for (int i = 0; i < 16; i++) {
        int idx = t + 256 * i;
        int r = idx >> 4, c = idx & 15;
        float4 v = W24[r * 16 + c];
        *(uint2*)(sW2 + r * W2LD + c * 4) = f4_to_h4(v);
    }
#pragma unroll
    for (int i = 0; i < 16; i++) {
        int idx = t + 256 * i;
        int n = idx >> 6, c = idx & 63;
        uint2 v = (n0 + n < Nn) ? g_x2h[(n0 + n) * 64 + c] : make_uint2(0u, 0u);
        *(uint2*)(sX2 + n * X2LD + c * 4) = v;
    }
    __syncthreads();

    int w = t >> 5;
    int wm = w & 1;
    int wn = w >> 1;
    wmma::fragment<wmma::accumulator, 16, 16, 16, float> c[2];
    wmma::fill_fragment(c[0], 0.f);
    wmma::fill_fragment(c[1], 0.f);

#pragma unroll
    for (int kk = 0; kk < 16; kk++) {
        wmma::fragment<wmma::matrix_a, 16, 16, 16, __half, wmma::row_major> a[2];
        wmma::fragment<wmma::matrix_b, 16, 16, 16, __half, wmma::row_major> b;
        wmma::load_matrix_sync(a[0], sX2 + (wm * 32) * X2LD + kk * 16, X2LD);
        wmma::load_matrix_sync(a[1], sX2 + (wm * 32 + 16) * X2LD + kk * 16, X2LD);
        wmma::load_matrix_sync(b, sW2 + (kk * 16) * W2LD + wn * 16, W2LD);
        wmma::mma_sync(c[0], a[0], b, c[0]);
        wmma::mma_sync(c[1], a[1], b, c[1]);
    }
    __syncthreads();
    wmma::store_matrix_sync(sC2 + (wm * 32) * W2LD + wn * 16, c[0], W2LD, wmma::mem_row_major);
    wmma::store_matrix_sync(sC2 + (wm * 32 + 16) * W2LD + wn * 16, c[1], W2LD, wmma::mem_row_major);
    __syncthreads();

#pragma unroll
    for (int i = 0; i < 4; i++) {
        int idx = t + 256 * i;
        int n = idx >> 4, g = idx & 15;
        if (n0 + n < Nn) {
            float4 v = *(const float4*)(sC2 + n * W2LD + g * 4);
            ((uint2*)g_h2h)[(n0 + n) * 16 + g] = f4_to_h4(v);
        }
    }

    {
        int node = t >> 2, q = t & 3;
        const float* cv = sC2 + node * W2LD + q * 16;
        const float* av = as2 + q * 16;
        const float* dv = ad2 + q * 16;
        float ps = 0.f, pd = 0.f;
#pragma unroll
        for (int j = 0; j < 16; j++) {
            float v = cv[j];
            ps += v * av[j];
            pd += v * dv[j];
        }
        ps += __shfl_down_sync(0xFFFFFFFFu, ps, 2, 4);
        ps += __shfl_down_sync(0xFFFFFFFFu, ps, 1, 4);
        pd += __shfl_down_sync(0xFFFFFFFFu, pd, 2, 4);
        pd += __shfl_down_sync(0xFFFFFFFFu, pd, 1, 4);
        if (q == 0) {
            int n = n0 + node;
            if (n < Nn) { g_ss2[n] = ps; g_sd2[n] = pd; }
        }
    }
}

// ---------------- layer 2 gather-aggregate + column-min + final write -------
__global__ void k_agg2(const float* __restrict__ b2, float* __restrict__ out) {
    __shared__ float smin[8 * 64];
    __shared__ int isLast;
    int w = threadIdx.x >> 5;
    int l = threadIdx.x & 31;
    int d = (blockIdx.x << 3) + w;

    float v0 = CUDART_INF_F, v1 = CUDART_INF_F;
    if (d < Nn) {
        int deg = g_cnt[d];
        if (deg > CAP) deg = CAP;
        float sdd = g_sd2[d];
        const unsigned* h2r = (const unsigned*)g_h2h;
        const int* bkt = g_bkt + d * CAP;

        float wself = __expf(lrelu(g_ss2[d] + sdd));
        float a0, a1;
        {
            unsigned ps = h2r[d * 32 + l];
            float2 f = __half22float2(*(__half2*)&ps);
            a0 = wself * f.x;
            a1 = wself * f.y;
        }
        float den_own = 0.f;
        const __half2 hz = __half2half2(__ushort_as_half(0));

        for (int base = 0; base < deg; base += 32) {
            int sv = (base + l < deg) ? bkt[base + l] : 0;
            int m = deg - base; if (m > 32) m = 32;
            int jj = 0;
            for (; jj + 8 <= m; jj += 8) {
                int s[8];
#pragma unroll
                for (int u = 0; u < 8; u++) s[u] = __shfl_sync(0xFFFFFFFFu, sv, jj + u);
                unsigned p[8];
#pragma unroll
                for (int u = 0; u < 8; u++) p[u] = h2r[s[u] * 32 + l];
                int u0 = l & 7;
                float e = g_ss2[s[u0]];
                float wown = __expf(lrelu(e + sdd));
                den_own += wown;          // 4 replicas per edge; groups reduce identically
                unsigned wpk;
                { __half2 tt = __half2half2(__float2half_rn(wown)); wpk = *(unsigned*)&tt; }
                __half2 ha = hz;
#pragma unroll
                for (int u = 0; u < 8; u++) {
                    unsigned wu = __shfl_sync(0xFFFFFFFFu, wpk, (l & 24) | u);
                    ha = __hfma2(*(__half2*)&wu, *(__half2*)&p[u], ha);
                }
                float2 f = __half22float2(ha);
                a0 += f.x;
                a1 += f.y;
            }
            for (; jj < m; jj++) {
                int s = __shfl_sync(0xFFFFFFFFu, sv, jj);
                float wgt = __expf(lrelu(g_ss2[s] + sdd));
                unsigned p = h2r[s * 32 + l];
                float2 f = __half22float2(*(__half2*)&p);
                a0 += wgt * f.x;
                a1 += wgt * f.y;
                if ((l & 7) == 0) den_own += wgt;
            }
        }
        float den = den_own;
        den += __shfl_xor_sync(0xFFFFFFFFu, den, 1, 8);
        den += __shfl_xor_sync(0xFFFFFFFFu, den, 2, 8);
        den += __shfl_xor_sync(0xFFFFFFFFu, den, 4, 8);
        den += wself;

        float r = 1.f / den;
        v0 = a0 * r + b2[2 * l];
        v1 = a1 * r + b2[2 * l + 1];
        if (l == 0) g_cnt[d] = 0;            // reset cursor for next call
    }
    smin[w * 64 + 2 * l] = v0;
    smin[w * 64 + 2 * l + 1] = v1;
    __syncthreads();
    if (threadIdx.x < 64) {
        int f = threadIdx.x;
        float m = smin[f];
#pragma unroll
        for (int i = 1; i < 8; i++) m = fminf(m, smin[i * 64 + f]);
        atomicMin(&g_minbuf[f], fenc(m));
    }
    __syncthreads();
    __threadfence();
    if (threadIdx.x == 0)
        isLast = (atomicAdd(&g_done, 1) == gridDim.x - 1);
    __syncthreads();
    if (isLast) {
        if (threadIdx.x < 64) {
            out[threadIdx.x] = fdec(g_minbuf[threadIdx.x]);
            g_minbuf[threadIdx.x] = 0xFFFFFFFFu;
        }
        if (threadIdx.x == 0) g_done = 0;
    }
}

// ---------------- side stream + events ----------------
struct SideStream {
    cudaStream_t s;
    cudaEvent_t evF, evJ;
    SideStream() {
        cudaStreamCreateWithFlags(&s, cudaStreamNonBlocking);
        cudaEventCreateWithFlags(&evF, cudaEventDisableTiming);
        cudaEventCreateWithFlags(&evJ, cudaEventDisableTiming);
    }
};
static SideStream g_side;

// ---------------- launch ----------------
extern "C" void kernel_launch(void* const* d_in, const int* in_sizes, int n_in,
                              void* d_out, int out_size) {
    const float* x   = (const float*)d_in[0];
    const int*   ei  = (const int*)d_in[1];
    const float* W1  = (const float*)d_in[2];
    const float* as1 = (const float*)d_in[3];
    const float* ad1 = (const float*)d_in[4];
    const float* b1  = (const float*)d_in[5];
    const float* W2  = (const float*)d_in[6];
    const float* as2 = (const float*)d_in[7];
    const float* ad2 = (const float*)d_in[8];
    const float* b2  = (const float*)d_in[9];
    float* out = (float*)d_out;

    static int configured = 0;
    if (!configured) {
        cudaFuncSetAttribute(k_gemm1, cudaFuncAttributeMaxDynamicSharedMemorySize, SMEM1_BYTES);
        cudaFuncSetAttribute(k_gemm2, cudaFuncAttributeMaxDynamicSharedMemorySize, SMEM2_BYTES);
        configured = 1;
    }

    const int4* src4 = (const int4*)ei;
    const int4* dst4 = (const int4*)(ei + Ee);

    // fork: bucket build on side stream, concurrent with gemm1
    cudaEventRecord(g_side.evF, 0);
    cudaStreamWaitEvent(g_side.s, g_side.evF, 0);
    k_fillB<<<(Ee / 4 + 255) / 256, 256, 0, g_side.s>>>(src4, dst4);   // 0
    k_nop<<<1, 32, 0, g_side.s>>>();                                   // 1
    cudaEventRecord(g_side.evJ, g_side.s);

    dim3 g1((Nn + 63) / 64, 2);
    k_gemm1<<<g1, 256, SMEM1_BYTES>>>((const float4*)x, (const float4*)W1,
                                      (const float4*)as1, (const float4*)ad1);  // 2

    cudaStreamWaitEvent(0, g_side.evJ, 0);

    k_agg1<<<(Nn + 7) / 8, 256>>>((const float4*)b1);                  // 3 (profiled)
    k_gemm2<<<(Nn + 63) / 64, 256, SMEM2_BYTES>>>((const float4*)W2, as2, ad2);
    k_agg2<<<(Nn + 7) / 8, 256>>>(b2, out);
}